// round 13
// baseline (speedup 1.0000x reference)
#include <cuda_runtime.h>
#include <cuda_fp16.h>
#include <math.h>
#include <stdint.h>

#define Bb 8
#define Tt 1024
#define Cc 1024
#define NHEAD 16
#define HDIM 64
#define BHt (Bb*NHEAD)     // 128
#define Mm (Bb*Tt)         // 8192
#define N1 (3*Cc)          // 3072
#define KT 32              // 1024/32 k-tiles

// ------------------------- device scratch (no allocs allowed) --------------
__device__ __half g_xh [(size_t)Mm*Cc];
__device__ __half g_w1h[(size_t)N1*Cc];
__device__ __half g_w2h[(size_t)Cc*Cc];
__device__ __half g_yh [(size_t)Mm*Cc];
__device__ __half g_Qh [(size_t)BHt*Tt*HDIM];   // post-rope, x0.125
__device__ __half g_Kh [(size_t)BHt*Tt*HDIM];   // post-rope
__device__ __half g_Vth[(size_t)BHt*HDIM*Tt];   // [bh][d][t]

// ------------------------------ PTX helpers --------------------------------
__device__ __forceinline__ uint32_t smem_u32(const void* p) {
    uint32_t a;
    asm("{ .reg .u64 t; cvta.to.shared.u64 t, %1; cvt.u32.u64 %0, t; }"
        : "=r"(a) : "l"(p));
    return a;
}

#define CP16(dst, src) \
    asm volatile("cp.async.cg.shared.global [%0], [%1], 16;" \
                 :: "r"(dst), "l"(src) : "memory")
#define CP_COMMIT() asm volatile("cp.async.commit_group;" ::: "memory")
#define CP_WAIT0()  asm volatile("cp.async.wait_group 0;" ::: "memory")

#define LDSM4(r0, r1, r2, r3, a) \
    asm volatile("ldmatrix.sync.aligned.m8n8.x4.shared.b16 {%0,%1,%2,%3}, [%4];" \
                 : "=r"(r0), "=r"(r1), "=r"(r2), "=r"(r3) : "r"(a))

__device__ __forceinline__ void mma16816(float c[4], const uint32_t a[4],
                                         uint32_t b0, uint32_t b1) {
    asm volatile("mma.sync.aligned.m16n8k16.row.col.f32.f16.f16.f32 "
                 "{%0,%1,%2,%3}, {%4,%5,%6,%7}, {%8,%9}, {%0,%1,%2,%3};"
                 : "+f"(c[0]), "+f"(c[1]), "+f"(c[2]), "+f"(c[3])
                 : "r"(a[0]), "r"(a[1]), "r"(a[2]), "r"(a[3]),
                   "r"(b0), "r"(b1));
}

__device__ __forceinline__ uint32_t pack2h(float x, float y) {
    __half2 h = __floats2half2_rn(x, y);
    return *reinterpret_cast<uint32_t*>(&h);
}

// ---------------------------------------------------------------------------
// fp32 -> fp16 conversion (single).  W=0: x.  W=1: w1.  W=2: w2.
// ---------------------------------------------------------------------------
template<int W>
__global__ __launch_bounds__(256)
void cvt_kernel(const float* __restrict__ src, int n4)
{
    int i = blockIdx.x * blockDim.x + threadIdx.x;
    if (i >= n4) return;
    float4 v = ((const float4*)src)[i];
    uint2 o = make_uint2(pack2h(v.x, v.y), pack2h(v.z, v.w));
    if (W == 0)      ((uint2*)g_xh)[i]  = o;
    else if (W == 1) ((uint2*)g_w1h)[i] = o;
    else             ((uint2*)g_w2h)[i] = o;
}

// ---------------------------------------------------------------------------
// fp16 NT GEMM via mma.sync: 128x128 block, 256 thr, 8 warps (2x4, 64x32).
// Single sync per k-tile: wait<0>; sync; prefetch(kt+1); compute(kt).
// MODE 0: qkv = x @ w1^T + b, fused RoPE epilogue.  MODE 1: y @ w2^T + b.
// ---------------------------------------------------------------------------
#define T_AH 0
#define T_BH 10240
#define STAGE_BYTES 20480
#define GEMM_SMEM (2*STAGE_BYTES)

#define ROPE_LN_OVER_32 0.2878231366242557f   // ln(10000)/32

__device__ __forceinline__ void gemm_prefetch(uint32_t sdst,
    const __half* a_h, const __half* b_h)
{
    CP16(sdst + T_AH,      a_h);
    CP16(sdst + T_AH + 16, a_h + 8);
    CP16(sdst + T_BH,      b_h);
    CP16(sdst + T_BH + 16, b_h + 8);
}

// Epilogue scatter with fused RoPE. v = (col d, col d+1), d even.
__device__ __forceinline__ void scatter_qkv(int m, int n, float2 v)
{
    const int which = n >> 10, c = n & 1023;
    const int h = c >> 6, d = c & 63;
    const int b = m >> 10, t = m & 1023, bh = b * NHEAD + h;
    if (which == 2) {
        size_t i0 = ((size_t)bh * HDIM + d) * Tt + t;
        g_Vth[i0]      = __float2half(v.x);
        g_Vth[i0 + Tt] = __float2half(v.y);
        return;
    }
    const float inv = expf(-(float)(d >> 1) * ROPE_LN_OVER_32);
    float sv, cv;
    sincosf((float)t * inv, &sv, &cv);
    float r1 = v.x * cv - v.y * sv;
    float r2 = v.y * cv + v.x * sv;
    const size_t base = ((size_t)bh * Tt + t) * HDIM + d;
    if (which == 0) {
        *(uint32_t*)&g_Qh[base] = pack2h(r1 * 0.125f, r2 * 0.125f);
    } else {
        *(uint32_t*)&g_Kh[base] = pack2h(r1, r2);
    }
}

template<int MODE>
__global__ __launch_bounds__(256)
void gemm_fp16(const float* __restrict__ bias, float* __restrict__ Cout)
{
    extern __shared__ char smem[];
    const uint32_t sb = smem_u32(smem);
    const int tid  = threadIdx.x;
    const int lane = tid & 31, wid = tid >> 5;
    const int wm = wid >> 2, wn = wid & 3;         // 2 x 4 warp grid, 64x32 tiles
    const int m0 = blockIdx.y * 128, n0 = blockIdx.x * 128;

    const __half* Ah = (MODE == 0) ? g_xh  : g_yh;
    const __half* Bh = (MODE == 0) ? g_w1h : g_w2h;

    const int lr = tid >> 1;
    const int lh = tid & 1;
    const size_t gA = (size_t)(m0 + lr) * Cc + lh * 16;
    const size_t gB = (size_t)(n0 + lr) * Cc + lh * 16;
    const uint32_t sOff = (uint32_t)lr * 80 + lh * 32;

    const int jq = lane >> 3, rr = lane & 7;
    const int aRow  = wm * 64 + (jq & 1) * 8 + rr;
    const int aColB = (jq >> 1) * 16;
    const int bRow  = wn * 32 + (jq >> 1) * 8 + rr;
    const int bColB = (jq & 1) * 16;

    float acc[4][4][4];
    #pragma unroll
    for (int i = 0; i < 4; i++)
        #pragma unroll
        for (int j = 0; j < 4; j++)
            #pragma unroll
            for (int e = 0; e < 4; e++) acc[i][j][e] = 0.0f;

    gemm_prefetch(sb + sOff, Ah + gA, Bh + gB);
    CP_COMMIT();

    for (int kt = 0; kt < KT; kt++) {
        CP_WAIT0();
        __syncthreads();           // stage kt visible; stage (kt+1)&1 free
        if (kt + 1 < KT) {
            const size_t ko = (size_t)(kt + 1) * 32;
            gemm_prefetch(sb + ((kt + 1) & 1) * STAGE_BYTES + sOff,
                          Ah + gA + ko, Bh + gB + ko);
            CP_COMMIT();
        }

        const uint32_t base = sb + (kt & 1) * STAGE_BYTES;
        #pragma unroll
        for (int kk = 0; kk < 2; kk++) {
            const uint32_t kB = kk * 32;
            uint32_t ah[4][4], bh[2][4];
            #pragma unroll
            for (int mf = 0; mf < 4; mf++) {
                uint32_t addr = base + (uint32_t)(aRow + mf * 16) * 80 + aColB + kB;
                LDSM4(ah[mf][0], ah[mf][1], ah[mf][2], ah[mf][3], addr + T_AH);
            }
            #pragma unroll
            for (int pf = 0; pf < 2; pf++) {
                uint32_t addr = base + (uint32_t)(bRow + pf * 16) * 80 + bColB + kB;
                LDSM4(bh[pf][0], bh[pf][1], bh[pf][2], bh[pf][3], addr + T_BH);
            }
            #pragma unroll
            for (int mf = 0; mf < 4; mf++) {
                #pragma unroll
                for (int nt = 0; nt < 4; nt++) {
                    const int pf = nt >> 1, ix = (nt & 1) * 2;
                    mma16816(acc[mf][nt], ah[mf], bh[pf][ix], bh[pf][ix + 1]);
                }
            }
        }
    }

    const int gid = lane >> 2, tg = lane & 3;
    #pragma unroll
    for (int mf = 0; mf < 4; mf++) {
        #pragma unroll
        for (int nt = 0; nt < 4; nt++) {
            const int n = n0 + wn * 32 + nt * 8 + tg * 2;
            const float2 bv = *(const float2*)&bias[n];
            const int mA = m0 + wm * 64 + mf * 16 + gid;
            float2 v01 = make_float2(acc[mf][nt][0] + bv.x, acc[mf][nt][1] + bv.y);
            float2 v23 = make_float2(acc[mf][nt][2] + bv.x, acc[mf][nt][3] + bv.y);
            if (MODE == 0) {
                scatter_qkv(mA,     n, v01);
                scatter_qkv(mA + 8, n, v23);
            } else {
                *(float2*)&Cout[(size_t)mA * Cc + n]       = v01;
                *(float2*)&Cout[(size_t)(mA + 8) * Cc + n] = v23;
            }
        }
    }
}

// ---------------------------------------------------------------------------
// Tensor-core flash attention (fp16), causal. Block = (qt, bh), 128 thr.
// K/V double-buffered via cp.async; single sync per k-tile.
// Smem: Qh (9216) + 2 x (Kh 9216 + Vh 9216) = 46080 B, pitch 144B.
// ---------------------------------------------------------------------------
#define FPITCH 144
#define SQH 0
#define SKV0 9216
#define KV_STAGE 18432
#define FL_SMEM 46080

__global__ __launch_bounds__(128)
void flash_attn_kernel()
{
    extern __shared__ char smem[];
    const uint32_t sb = smem_u32(smem);
    const int tid  = threadIdx.x;
    const int lane = tid & 31, w = tid >> 5;
    const int qt = blockIdx.x;     // 0..15
    const int bh = blockIdx.y;     // 0..127

    const __half* Qh = g_Qh  + ((size_t)bh * Tt + qt * 64) * HDIM;
    const __half* Kh = g_Kh  + (size_t)bh * Tt * HDIM;
    const __half* Vh = g_Vth + (size_t)bh * HDIM * Tt;

    // Q tile load (plain, once)
    #pragma unroll
    for (int ii = 0; ii < 4; ii++) {
        int idx = tid + 128 * ii;
        int r = idx >> 3, c8 = (idx & 7) * 8;
        uint32_t so = (uint32_t)r * FPITCH + c8 * 2;
        *(uint4*)(smem + SQH + so) = *(const uint4*)&Qh[r * 64 + c8];
    }

    const int jq = lane >> 3, rr = lane & 7;
    const uint32_t aAddr = sb + (uint32_t)(w * 16 + (lane & 15)) * FPITCH
                         + (lane >> 4) * 16;
    const uint32_t bBase = (uint32_t)((jq >> 1) * 8 + rr) * FPITCH
                         + (jq & 1) * 16;

    const int gid = lane >> 2, tg = lane & 3;
    const int rowA = w * 16 + gid;
    const int rowB = rowA + 8;

    float o[8][4];
    #pragma unroll
    for (int nt = 0; nt < 8; nt++)
        #pragma unroll
        for (int e = 0; e < 4; e++) o[nt][e] = 0.0f;
    float mA = -1e30f, mB = -1e30f, lA = 0.0f, lB = 0.0f;

    // prologue: prefetch kt=0 into stage 0
    #pragma unroll
    for (int ii = 0; ii < 4; ii++) {
        int idx = tid + 128 * ii;
        int r = idx >> 3, c8 = (idx & 7) * 8;
        uint32_t so = (uint32_t)r * FPITCH + c8 * 2;
        CP16(sb + SKV0 + so,        &Kh[(size_t)r * 64 + c8]);
        CP16(sb + SKV0 + 9216 + so, &Vh[(size_t)r * Tt + c8]);
    }
    CP_COMMIT();

    for (int kt = 0; kt <= qt; kt++) {
        CP_WAIT0();
        __syncthreads();          // stage kt&1 ready + other stage free
        if (kt < qt) {
            const uint32_t sdst = sb + SKV0 + ((kt + 1) & 1) * KV_STAGE;
            #pragma unroll
            for (int ii = 0; ii < 4; ii++) {
                int idx = tid + 128 * ii;
                int r = idx >> 3, c8 = (idx & 7) * 8;
                uint32_t so = (uint32_t)r * FPITCH + c8 * 2;
                CP16(sdst + so,        &Kh[((kt + 1) * 64 + r) * 64 + c8]);
                CP16(sdst + 9216 + so, &Vh[(size_t)r * Tt + (kt + 1) * 64 + c8]);
            }
            CP_COMMIT();
        }

        const uint32_t kvb = sb + SKV0 + (kt & 1) * KV_STAGE;

        float c[8][4];
        #pragma unroll
        for (int nt = 0; nt < 8; nt++)
            #pragma unroll
            for (int e = 0; e < 4; e++) c[nt][e] = 0.0f;

        #pragma unroll
        for (int kk = 0; kk < 4; kk++) {
            uint32_t aH[4];
            LDSM4(aH[0], aH[1], aH[2], aH[3], aAddr + SQH + kk * 32);
            #pragma unroll
            for (int pf = 0; pf < 4; pf++) {
                uint32_t bH[4];
                uint32_t ba = kvb + bBase + (uint32_t)pf * 16 * FPITCH + kk * 32;
                LDSM4(bH[0], bH[1], bH[2], bH[3], ba);
                const int nt0 = pf * 2;
                mma16816(c[nt0],     aH, bH[0], bH[1]);
                mma16816(c[nt0 + 1], aH, bH[2], bH[3]);
            }
        }

        if (kt == qt) {
            #pragma unroll
            for (int nt = 0; nt < 8; nt++) {
                const int colb = nt * 8 + tg * 2;
                if (colb     > rowA) c[nt][0] = -1e30f;
                if (colb + 1 > rowA) c[nt][1] = -1e30f;
                if (colb     > rowB) c[nt][2] = -1e30f;
                if (colb + 1 > rowB) c[nt][3] = -1e30f;
            }
        }

        float tmA = -1e30f, tmB = -1e30f;
        #pragma unroll
        for (int nt = 0; nt < 8; nt++) {
            tmA = fmaxf(tmA, fmaxf(c[nt][0], c[nt][1]));
            tmB = fmaxf(tmB, fmaxf(c[nt][2], c[nt][3]));
        }
        tmA = fmaxf(tmA, __shfl_xor_sync(0xffffffffu, tmA, 1));
        tmA = fmaxf(tmA, __shfl_xor_sync(0xffffffffu, tmA, 2));
        tmB = fmaxf(tmB, __shfl_xor_sync(0xffffffffu, tmB, 1));
        tmB = fmaxf(tmB, __shfl_xor_sync(0xffffffffu, tmB, 2));

        const float mnA = fmaxf(mA, tmA), mnB = fmaxf(mB, tmB);
        const float alA = __expf(mA - mnA), alB = __expf(mB - mnB);
        mA = mnA; mB = mnB;

        float sA = 0.0f, sB = 0.0f;
        #pragma unroll
        for (int nt = 0; nt < 8; nt++) {
            c[nt][0] = __expf(c[nt][0] - mnA); sA += c[nt][0];
            c[nt][1] = __expf(c[nt][1] - mnA); sA += c[nt][1];
            c[nt][2] = __expf(c[nt][2] - mnB); sB += c[nt][2];
            c[nt][3] = __expf(c[nt][3] - mnB); sB += c[nt][3];
        }
        sA += __shfl_xor_sync(0xffffffffu, sA, 1);
        sA += __shfl_xor_sync(0xffffffffu, sA, 2);
        sB += __shfl_xor_sync(0xffffffffu, sB, 1);
        sB += __shfl_xor_sync(0xffffffffu, sB, 2);
        lA = lA * alA + sA;
        lB = lB * alB + sB;
        #pragma unroll
        for (int nt = 0; nt < 8; nt++) {
            o[nt][0] *= alA; o[nt][1] *= alA;
            o[nt][2] *= alB; o[nt][3] *= alB;
        }

        #pragma unroll
        for (int ks = 0; ks < 4; ks++) {
            uint32_t pH[4];
            pH[0] = pack2h(c[2*ks][0],     c[2*ks][1]);
            pH[1] = pack2h(c[2*ks][2],     c[2*ks][3]);
            pH[2] = pack2h(c[2*ks + 1][0], c[2*ks + 1][1]);
            pH[3] = pack2h(c[2*ks + 1][2], c[2*ks + 1][3]);
            #pragma unroll
            for (int pfd = 0; pfd < 4; pfd++) {
                uint32_t bH[4];
                uint32_t ba = kvb + 9216 + bBase + (uint32_t)pfd * 16 * FPITCH + ks * 32;
                LDSM4(bH[0], bH[1], bH[2], bH[3], ba);
                const int nd = pfd * 2;
                mma16816(o[nd],     pH, bH[0], bH[1]);
                mma16816(o[nd + 1], pH, bH[2], bH[3]);
            }
        }
    }

    const int b = bh >> 4, h = bh & 15;
    const float invA = 1.0f / lA, invB = 1.0f / lB;
    const size_t ybA = ((size_t)(b * Tt + qt * 64 + rowA)) * Cc + h * HDIM;
    const size_t ybB = ((size_t)(b * Tt + qt * 64 + rowB)) * Cc + h * HDIM;
    #pragma unroll
    for (int nt = 0; nt < 8; nt++) {
        const int d = nt * 8 + tg * 2;
        *(uint32_t*)&g_yh[ybA + d] = pack2h(o[nt][0] * invA, o[nt][1] * invA);
        *(uint32_t*)&g_yh[ybB + d] = pack2h(o[nt][2] * invB, o[nt][3] * invB);
    }
}

// ---------------------------------------------------------------------------
extern "C" void kernel_launch(void* const* d_in, const int* in_sizes, int n_in,
                              void* d_out, int out_size)
{
    (void)in_sizes; (void)n_in; (void)out_size;
    const float* x   = (const float*)d_in[0];
    const float* ipw = (const float*)d_in[1];
    const float* ipb = (const float*)d_in[2];
    const float* opw = (const float*)d_in[3];
    const float* opb = (const float*)d_in[4];
    float* out = (float*)d_out;

    // Request max dynamic smem AND full shared-memory carveout so the SM
    // runs in the 228KB config -> 5 GEMM CTAs (or 4 flash CTAs) resident
    // instead of 2 (the R12 occupancy limiter).
    cudaFuncSetAttribute(gemm_fp16<0>,
                         cudaFuncAttributeMaxDynamicSharedMemorySize, GEMM_SMEM);
    cudaFuncSetAttribute(gemm_fp16<1>,
                         cudaFuncAttributeMaxDynamicSharedMemorySize, GEMM_SMEM);
    cudaFuncSetAttribute(flash_attn_kernel,
                         cudaFuncAttributeMaxDynamicSharedMemorySize, FL_SMEM);
    cudaFuncSetAttribute(gemm_fp16<0>,
                         cudaFuncAttributePreferredSharedMemoryCarveout, 100);
    cudaFuncSetAttribute(gemm_fp16<1>,
                         cudaFuncAttributePreferredSharedMemoryCarveout, 100);
    cudaFuncSetAttribute(flash_attn_kernel,
                         cudaFuncAttributePreferredSharedMemoryCarveout, 100);

    // 0) fp16 conversions
    cvt_kernel<0><<<(Mm*Cc/4 + 255)/256, 256>>>(x,   Mm*Cc/4);
    cvt_kernel<1><<<(N1*Cc/4 + 255)/256, 256>>>(ipw, N1*Cc/4);
    cvt_kernel<2><<<(Cc*Cc/4 + 255)/256, 256>>>(opw, Cc*Cc/4);

    // 1) QKV projection + bias + fused RoPE -> Qh, Kh, Vt (fp16)
    {
        dim3 grid(N1 / 128, Mm / 128);
        gemm_fp16<0><<<grid, 256, GEMM_SMEM>>>(ipb, nullptr);
    }

    // 2) tensor-core causal flash attention (async K/V pipeline) -> g_yh
    {
        dim3 grid(Tt / 64, BHt);
        flash_attn_kernel<<<grid, 128, FL_SMEM>>>();
    }

    // 3) output projection + bias
    {
        dim3 grid(Cc / 128, Mm / 128);
        gemm_fp16<1><<<grid, 256, GEMM_SMEM>>>(opb, out);
    }
}

// round 14
// speedup vs baseline: 1.1150x; 1.1150x over previous
#include <cuda_runtime.h>
#include <cuda_fp16.h>
#include <math.h>
#include <stdint.h>

#define Bb 8
#define Tt 1024
#define Cc 1024
#define NHEAD 16
#define HDIM 64
#define BHt (Bb*NHEAD)     // 128
#define Mm (Bb*Tt)         // 8192
#define N1 (3*Cc)          // 3072
#define KT 32              // 1024/32 k-tiles

// ------------------------- device scratch (no allocs allowed) --------------
__device__ __half g_xh [(size_t)Mm*Cc];
__device__ __half g_w1h[(size_t)N1*Cc];
__device__ __half g_w2h[(size_t)Cc*Cc];
__device__ __half g_yh [(size_t)Mm*Cc];
__device__ __half g_Qh [(size_t)BHt*Tt*HDIM];   // post-rope, x0.125
__device__ __half g_Kh [(size_t)BHt*Tt*HDIM];   // post-rope
__device__ __half g_Vth[(size_t)BHt*HDIM*Tt];   // [bh][d][t]

// ------------------------------ PTX helpers --------------------------------
__device__ __forceinline__ uint32_t smem_u32(const void* p) {
    uint32_t a;
    asm("{ .reg .u64 t; cvta.to.shared.u64 t, %1; cvt.u32.u64 %0, t; }"
        : "=r"(a) : "l"(p));
    return a;
}

#define CP16(dst, src) \
    asm volatile("cp.async.cg.shared.global [%0], [%1], 16;" \
                 :: "r"(dst), "l"(src) : "memory")
#define CP_COMMIT() asm volatile("cp.async.commit_group;" ::: "memory")
#define CP_WAIT0()  asm volatile("cp.async.wait_group 0;" ::: "memory")

#define LDSM4(r0, r1, r2, r3, a) \
    asm volatile("ldmatrix.sync.aligned.m8n8.x4.shared.b16 {%0,%1,%2,%3}, [%4];" \
                 : "=r"(r0), "=r"(r1), "=r"(r2), "=r"(r3) : "r"(a))

__device__ __forceinline__ void mma16816(float c[4], const uint32_t a[4],
                                         uint32_t b0, uint32_t b1) {
    asm volatile("mma.sync.aligned.m16n8k16.row.col.f32.f16.f16.f32 "
                 "{%0,%1,%2,%3}, {%4,%5,%6,%7}, {%8,%9}, {%0,%1,%2,%3};"
                 : "+f"(c[0]), "+f"(c[1]), "+f"(c[2]), "+f"(c[3])
                 : "r"(a[0]), "r"(a[1]), "r"(a[2]), "r"(a[3]),
                   "r"(b0), "r"(b1));
}

__device__ __forceinline__ uint32_t pack2h(float x, float y) {
    __half2 h = __floats2half2_rn(x, y);
    return *reinterpret_cast<uint32_t*>(&h);
}

// ---------------------------------------------------------------------------
// fp32 -> fp16 conversion (single).  W=0: x.  W=1: w1.  W=2: w2.
// ---------------------------------------------------------------------------
template<int W>
__global__ __launch_bounds__(256)
void cvt_kernel(const float* __restrict__ src, int n4)
{
    int i = blockIdx.x * blockDim.x + threadIdx.x;
    if (i >= n4) return;
    float4 v = ((const float4*)src)[i];
    uint2 o = make_uint2(pack2h(v.x, v.y), pack2h(v.z, v.w));
    if (W == 0)      ((uint2*)g_xh)[i]  = o;
    else if (W == 1) ((uint2*)g_w1h)[i] = o;
    else             ((uint2*)g_w2h)[i] = o;
}

// ---------------------------------------------------------------------------
// fp16 NT GEMM via mma.sync: 64x128 block, 256 thr, 8 warps (2x4, 32x32 warp
// tiles). ~70 regs/thread -> 3 CTAs/SM (RF was the occupancy limiter).
// Single sync per k-tile; double-buffered cp.async; 80B pitch smem.
// MODE 0: qkv = x @ w1^T + b, fused RoPE epilogue.  MODE 1: y @ w2^T + b.
// ---------------------------------------------------------------------------
#define T_AH 0
#define T_BH 5120           // 64 rows * 80B
#define STAGE_BYTES 15360   // (64 + 128) rows * 80B
#define GEMM_SMEM (2*STAGE_BYTES)

#define ROPE_LN_OVER_32 0.2878231366242557f   // ln(10000)/32

// Epilogue scatter with fused RoPE. v = (col d, col d+1), d even.
__device__ __forceinline__ void scatter_qkv(int m, int n, float2 v)
{
    const int which = n >> 10, c = n & 1023;
    const int h = c >> 6, d = c & 63;
    const int b = m >> 10, t = m & 1023, bh = b * NHEAD + h;
    if (which == 2) {
        size_t i0 = ((size_t)bh * HDIM + d) * Tt + t;
        g_Vth[i0]      = __float2half(v.x);
        g_Vth[i0 + Tt] = __float2half(v.y);
        return;
    }
    const float inv = expf(-(float)(d >> 1) * ROPE_LN_OVER_32);
    float sv, cv;
    sincosf((float)t * inv, &sv, &cv);
    float r1 = v.x * cv - v.y * sv;
    float r2 = v.y * cv + v.x * sv;
    const size_t base = ((size_t)bh * Tt + t) * HDIM + d;
    if (which == 0) {
        *(uint32_t*)&g_Qh[base] = pack2h(r1 * 0.125f, r2 * 0.125f);
    } else {
        *(uint32_t*)&g_Kh[base] = pack2h(r1, r2);
    }
}

template<int MODE>
__global__ __launch_bounds__(256, 3)
void gemm_fp16(const float* __restrict__ bias, float* __restrict__ Cout)
{
    extern __shared__ char smem[];
    const uint32_t sb = smem_u32(smem);
    const int tid  = threadIdx.x;
    const int lane = tid & 31, wid = tid >> 5;
    const int wm = wid >> 2, wn = wid & 3;         // 2 x 4 warp grid, 32x32 tiles
    const int m0 = blockIdx.y * 64, n0 = blockIdx.x * 128;

    const __half* Ah = (MODE == 0) ? g_xh  : g_yh;
    const __half* Bh = (MODE == 0) ? g_w1h : g_w2h;

    // cp.async: 768 16B pieces per stage (192 rows x 4), 3 per thread
    const __half* srcs[3];
    uint32_t soff[3];
    #pragma unroll
    for (int j = 0; j < 3; j++) {
        const int idx = tid + 256 * j;
        const int row = idx >> 2, c16 = idx & 3;
        soff[j] = (uint32_t)row * 80 + c16 * 16;
        srcs[j] = (row < 64)
                ? Ah + (size_t)(m0 + row) * Cc + c16 * 8
                : Bh + (size_t)(n0 + row - 64) * Cc + c16 * 8;
    }

    const int jq = lane >> 3, rr = lane & 7;
    const int aRow  = wm * 32 + (jq & 1) * 8 + rr;   // + mf*16
    const int aColB = (jq >> 1) * 16;                // + kk*32
    const int bRow  = wn * 32 + (jq >> 1) * 8 + rr;  // + pf*16
    const int bColB = (jq & 1) * 16;

    float acc[2][4][4];
    #pragma unroll
    for (int i = 0; i < 2; i++)
        #pragma unroll
        for (int j = 0; j < 4; j++)
            #pragma unroll
            for (int e = 0; e < 4; e++) acc[i][j][e] = 0.0f;

    #pragma unroll
    for (int j = 0; j < 3; j++) CP16(sb + soff[j], srcs[j]);
    CP_COMMIT();

    for (int kt = 0; kt < KT; kt++) {
        CP_WAIT0();
        __syncthreads();           // stage kt visible; stage (kt+1)&1 free
        if (kt + 1 < KT) {
            const uint32_t sdst = sb + ((kt + 1) & 1) * STAGE_BYTES;
            const int ko = (kt + 1) * 32;
            #pragma unroll
            for (int j = 0; j < 3; j++) CP16(sdst + soff[j], srcs[j] + ko);
            CP_COMMIT();
        }

        const uint32_t base = sb + (kt & 1) * STAGE_BYTES;
        #pragma unroll
        for (int kk = 0; kk < 2; kk++) {
            const uint32_t kB = kk * 32;
            uint32_t ah[2][4], bh[2][4];
            #pragma unroll
            for (int mf = 0; mf < 2; mf++) {
                uint32_t addr = base + (uint32_t)(aRow + mf * 16) * 80 + aColB + kB;
                LDSM4(ah[mf][0], ah[mf][1], ah[mf][2], ah[mf][3], addr + T_AH);
            }
            #pragma unroll
            for (int pf = 0; pf < 2; pf++) {
                uint32_t addr = base + (uint32_t)(bRow + pf * 16) * 80 + bColB + kB;
                LDSM4(bh[pf][0], bh[pf][1], bh[pf][2], bh[pf][3], addr + T_BH);
            }
            #pragma unroll
            for (int mf = 0; mf < 2; mf++) {
                #pragma unroll
                for (int nt = 0; nt < 4; nt++) {
                    const int pf = nt >> 1, ix = (nt & 1) * 2;
                    mma16816(acc[mf][nt], ah[mf], bh[pf][ix], bh[pf][ix + 1]);
                }
            }
        }
    }

    const int gid = lane >> 2, tg = lane & 3;
    #pragma unroll
    for (int mf = 0; mf < 2; mf++) {
        #pragma unroll
        for (int nt = 0; nt < 4; nt++) {
            const int n = n0 + wn * 32 + nt * 8 + tg * 2;
            const float2 bv = *(const float2*)&bias[n];
            const int mA = m0 + wm * 32 + mf * 16 + gid;
            float2 v01 = make_float2(acc[mf][nt][0] + bv.x, acc[mf][nt][1] + bv.y);
            float2 v23 = make_float2(acc[mf][nt][2] + bv.x, acc[mf][nt][3] + bv.y);
            if (MODE == 0) {
                scatter_qkv(mA,     n, v01);
                scatter_qkv(mA + 8, n, v23);
            } else {
                *(float2*)&Cout[(size_t)mA * Cc + n]       = v01;
                *(float2*)&Cout[(size_t)(mA + 8) * Cc + n] = v23;
            }
        }
    }
}

// ---------------------------------------------------------------------------
// Tensor-core flash attention (fp16), causal. Block = (qt, bh), 128 thr.
// K/V double-buffered via cp.async; single sync per k-tile.  (unchanged R12)
// ---------------------------------------------------------------------------
#define FPITCH 144
#define SQH 0
#define SKV0 9216
#define KV_STAGE 18432
#define FL_SMEM 46080

__global__ __launch_bounds__(128)
void flash_attn_kernel()
{
    extern __shared__ char smem[];
    const uint32_t sb = smem_u32(smem);
    const int tid  = threadIdx.x;
    const int lane = tid & 31, w = tid >> 5;
    const int qt = blockIdx.x;     // 0..15
    const int bh = blockIdx.y;     // 0..127

    const __half* Qh = g_Qh  + ((size_t)bh * Tt + qt * 64) * HDIM;
    const __half* Kh = g_Kh  + (size_t)bh * Tt * HDIM;
    const __half* Vh = g_Vth + (size_t)bh * HDIM * Tt;

    #pragma unroll
    for (int ii = 0; ii < 4; ii++) {
        int idx = tid + 128 * ii;
        int r = idx >> 3, c8 = (idx & 7) * 8;
        uint32_t so = (uint32_t)r * FPITCH + c8 * 2;
        *(uint4*)(smem + SQH + so) = *(const uint4*)&Qh[r * 64 + c8];
    }

    const int jq = lane >> 3, rr = lane & 7;
    const uint32_t aAddr = sb + (uint32_t)(w * 16 + (lane & 15)) * FPITCH
                         + (lane >> 4) * 16;
    const uint32_t bBase = (uint32_t)((jq >> 1) * 8 + rr) * FPITCH
                         + (jq & 1) * 16;

    const int gid = lane >> 2, tg = lane & 3;
    const int rowA = w * 16 + gid;
    const int rowB = rowA + 8;

    float o[8][4];
    #pragma unroll
    for (int nt = 0; nt < 8; nt++)
        #pragma unroll
        for (int e = 0; e < 4; e++) o[nt][e] = 0.0f;
    float mA = -1e30f, mB = -1e30f, lA = 0.0f, lB = 0.0f;

    #pragma unroll
    for (int ii = 0; ii < 4; ii++) {
        int idx = tid + 128 * ii;
        int r = idx >> 3, c8 = (idx & 7) * 8;
        uint32_t so = (uint32_t)r * FPITCH + c8 * 2;
        CP16(sb + SKV0 + so,        &Kh[(size_t)r * 64 + c8]);
        CP16(sb + SKV0 + 9216 + so, &Vh[(size_t)r * Tt + c8]);
    }
    CP_COMMIT();

    for (int kt = 0; kt <= qt; kt++) {
        CP_WAIT0();
        __syncthreads();
        if (kt < qt) {
            const uint32_t sdst = sb + SKV0 + ((kt + 1) & 1) * KV_STAGE;
            #pragma unroll
            for (int ii = 0; ii < 4; ii++) {
                int idx = tid + 128 * ii;
                int r = idx >> 3, c8 = (idx & 7) * 8;
                uint32_t so = (uint32_t)r * FPITCH + c8 * 2;
                CP16(sdst + so,        &Kh[((kt + 1) * 64 + r) * 64 + c8]);
                CP16(sdst + 9216 + so, &Vh[(size_t)r * Tt + (kt + 1) * 64 + c8]);
            }
            CP_COMMIT();
        }

        const uint32_t kvb = sb + SKV0 + (kt & 1) * KV_STAGE;

        float c[8][4];
        #pragma unroll
        for (int nt = 0; nt < 8; nt++)
            #pragma unroll
            for (int e = 0; e < 4; e++) c[nt][e] = 0.0f;

        #pragma unroll
        for (int kk = 0; kk < 4; kk++) {
            uint32_t aH[4];
            LDSM4(aH[0], aH[1], aH[2], aH[3], aAddr + SQH + kk * 32);
            #pragma unroll
            for (int pf = 0; pf < 4; pf++) {
                uint32_t bH[4];
                uint32_t ba = kvb + bBase + (uint32_t)pf * 16 * FPITCH + kk * 32;
                LDSM4(bH[0], bH[1], bH[2], bH[3], ba);
                const int nt0 = pf * 2;
                mma16816(c[nt0],     aH, bH[0], bH[1]);
                mma16816(c[nt0 + 1], aH, bH[2], bH[3]);
            }
        }

        if (kt == qt) {
            #pragma unroll
            for (int nt = 0; nt < 8; nt++) {
                const int colb = nt * 8 + tg * 2;
                if (colb     > rowA) c[nt][0] = -1e30f;
                if (colb + 1 > rowA) c[nt][1] = -1e30f;
                if (colb     > rowB) c[nt][2] = -1e30f;
                if (colb + 1 > rowB) c[nt][3] = -1e30f;
            }
        }

        float tmA = -1e30f, tmB = -1e30f;
        #pragma unroll
        for (int nt = 0; nt < 8; nt++) {
            tmA = fmaxf(tmA, fmaxf(c[nt][0], c[nt][1]));
            tmB = fmaxf(tmB, fmaxf(c[nt][2], c[nt][3]));
        }
        tmA = fmaxf(tmA, __shfl_xor_sync(0xffffffffu, tmA, 1));
        tmA = fmaxf(tmA, __shfl_xor_sync(0xffffffffu, tmA, 2));
        tmB = fmaxf(tmB, __shfl_xor_sync(0xffffffffu, tmB, 1));
        tmB = fmaxf(tmB, __shfl_xor_sync(0xffffffffu, tmB, 2));

        const float mnA = fmaxf(mA, tmA), mnB = fmaxf(mB, tmB);
        const float alA = __expf(mA - mnA), alB = __expf(mB - mnB);
        mA = mnA; mB = mnB;

        float sA = 0.0f, sB = 0.0f;
        #pragma unroll
        for (int nt = 0; nt < 8; nt++) {
            c[nt][0] = __expf(c[nt][0] - mnA); sA += c[nt][0];
            c[nt][1] = __expf(c[nt][1] - mnA); sA += c[nt][1];
            c[nt][2] = __expf(c[nt][2] - mnB); sB += c[nt][2];
            c[nt][3] = __expf(c[nt][3] - mnB); sB += c[nt][3];
        }
        sA += __shfl_xor_sync(0xffffffffu, sA, 1);
        sA += __shfl_xor_sync(0xffffffffu, sA, 2);
        sB += __shfl_xor_sync(0xffffffffu, sB, 1);
        sB += __shfl_xor_sync(0xffffffffu, sB, 2);
        lA = lA * alA + sA;
        lB = lB * alB + sB;
        #pragma unroll
        for (int nt = 0; nt < 8; nt++) {
            o[nt][0] *= alA; o[nt][1] *= alA;
            o[nt][2] *= alB; o[nt][3] *= alB;
        }

        #pragma unroll
        for (int ks = 0; ks < 4; ks++) {
            uint32_t pH[4];
            pH[0] = pack2h(c[2*ks][0],     c[2*ks][1]);
            pH[1] = pack2h(c[2*ks][2],     c[2*ks][3]);
            pH[2] = pack2h(c[2*ks + 1][0], c[2*ks + 1][1]);
            pH[3] = pack2h(c[2*ks + 1][2], c[2*ks + 1][3]);
            #pragma unroll
            for (int pfd = 0; pfd < 4; pfd++) {
                uint32_t bH[4];
                uint32_t ba = kvb + 9216 + bBase + (uint32_t)pfd * 16 * FPITCH + ks * 32;
                LDSM4(bH[0], bH[1], bH[2], bH[3], ba);
                const int nd = pfd * 2;
                mma16816(o[nd],     pH, bH[0], bH[1]);
                mma16816(o[nd + 1], pH, bH[2], bH[3]);
            }
        }
    }

    const int b = bh >> 4, h = bh & 15;
    const float invA = 1.0f / lA, invB = 1.0f / lB;
    const size_t ybA = ((size_t)(b * Tt + qt * 64 + rowA)) * Cc + h * HDIM;
    const size_t ybB = ((size_t)(b * Tt + qt * 64 + rowB)) * Cc + h * HDIM;
    #pragma unroll
    for (int nt = 0; nt < 8; nt++) {
        const int d = nt * 8 + tg * 2;
        *(uint32_t*)&g_yh[ybA + d] = pack2h(o[nt][0] * invA, o[nt][1] * invA);
        *(uint32_t*)&g_yh[ybB + d] = pack2h(o[nt][2] * invB, o[nt][3] * invB);
    }
}

// ---------------------------------------------------------------------------
extern "C" void kernel_launch(void* const* d_in, const int* in_sizes, int n_in,
                              void* d_out, int out_size)
{
    (void)in_sizes; (void)n_in; (void)out_size;
    const float* x   = (const float*)d_in[0];
    const float* ipw = (const float*)d_in[1];
    const float* ipb = (const float*)d_in[2];
    const float* opw = (const float*)d_in[3];
    const float* opb = (const float*)d_in[4];
    float* out = (float*)d_out;

    cudaFuncSetAttribute(gemm_fp16<0>,
                         cudaFuncAttributeMaxDynamicSharedMemorySize, GEMM_SMEM);
    cudaFuncSetAttribute(gemm_fp16<1>,
                         cudaFuncAttributeMaxDynamicSharedMemorySize, GEMM_SMEM);
    cudaFuncSetAttribute(flash_attn_kernel,
                         cudaFuncAttributeMaxDynamicSharedMemorySize, FL_SMEM);

    // 0) fp16 conversions
    cvt_kernel<0><<<(Mm*Cc/4 + 255)/256, 256>>>(x,   Mm*Cc/4);
    cvt_kernel<1><<<(N1*Cc/4 + 255)/256, 256>>>(ipw, N1*Cc/4);
    cvt_kernel<2><<<(Cc*Cc/4 + 255)/256, 256>>>(opw, Cc*Cc/4);

    // 1) QKV projection + bias + fused RoPE -> Qh, Kh, Vt (fp16)
    {
        dim3 grid(N1 / 128, Mm / 64);    // (24, 128)
        gemm_fp16<0><<<grid, 256, GEMM_SMEM>>>(ipb, nullptr);
    }

    // 2) tensor-core causal flash attention (async K/V pipeline) -> g_yh
    {
        dim3 grid(Tt / 64, BHt);
        flash_attn_kernel<<<grid, 128, FL_SMEM>>>();
    }

    // 3) output projection + bias
    {
        dim3 grid(Cc / 128, Mm / 64);    // (8, 128)
        gemm_fp16<1><<<grid, 256, GEMM_SMEM>>>(opb, out);
    }
}

// round 15
// speedup vs baseline: 1.1545x; 1.0354x over previous
#include <cuda_runtime.h>
#include <cuda_fp16.h>
#include <math.h>
#include <stdint.h>

#define Bb 8
#define Tt 1024
#define Cc 1024
#define NHEAD 16
#define HDIM 64
#define BHt (Bb*NHEAD)     // 128
#define Mm (Bb*Tt)         // 8192
#define N1 (3*Cc)          // 3072
#define KT 32              // 1024/32 k-tiles

// ------------------------- device scratch (no allocs allowed) --------------
__device__ __half g_xh [(size_t)Mm*Cc];
__device__ __half g_w1h[(size_t)N1*Cc];
__device__ __half g_w2h[(size_t)Cc*Cc];
__device__ __half g_yh [(size_t)Mm*Cc];
__device__ __half g_Qh [(size_t)BHt*Tt*HDIM];   // post-rope, x0.125
__device__ __half g_Kh [(size_t)BHt*Tt*HDIM];   // post-rope
__device__ __half g_Vth[(size_t)BHt*HDIM*Tt];   // [bh][d][t]

// ------------------------------ PTX helpers --------------------------------
__device__ __forceinline__ uint32_t smem_u32(const void* p) {
    uint32_t a;
    asm("{ .reg .u64 t; cvta.to.shared.u64 t, %1; cvt.u32.u64 %0, t; }"
        : "=r"(a) : "l"(p));
    return a;
}

#define CP16(dst, src) \
    asm volatile("cp.async.cg.shared.global [%0], [%1], 16;" \
                 :: "r"(dst), "l"(src) : "memory")
#define CP_COMMIT() asm volatile("cp.async.commit_group;" ::: "memory")
#define CP_WAIT0()  asm volatile("cp.async.wait_group 0;" ::: "memory")

#define LDSM4(r0, r1, r2, r3, a) \
    asm volatile("ldmatrix.sync.aligned.m8n8.x4.shared.b16 {%0,%1,%2,%3}, [%4];" \
                 : "=r"(r0), "=r"(r1), "=r"(r2), "=r"(r3) : "r"(a))

__device__ __forceinline__ void mma16816(float c[4], const uint32_t a[4],
                                         uint32_t b0, uint32_t b1) {
    asm volatile("mma.sync.aligned.m16n8k16.row.col.f32.f16.f16.f32 "
                 "{%0,%1,%2,%3}, {%4,%5,%6,%7}, {%8,%9}, {%0,%1,%2,%3};"
                 : "+f"(c[0]), "+f"(c[1]), "+f"(c[2]), "+f"(c[3])
                 : "r"(a[0]), "r"(a[1]), "r"(a[2]), "r"(a[3]),
                   "r"(b0), "r"(b1));
}

__device__ __forceinline__ uint32_t pack2h(float x, float y) {
    __half2 h = __floats2half2_rn(x, y);
    return *reinterpret_cast<uint32_t*>(&h);
}

// ---------------------------------------------------------------------------
// fp32 -> fp16 conversion (single).  W=0: x.  W=1: w1.  W=2: w2.
// ---------------------------------------------------------------------------
template<int W>
__global__ __launch_bounds__(256)
void cvt_kernel(const float* __restrict__ src, int n4)
{
    int i = blockIdx.x * blockDim.x + threadIdx.x;
    if (i >= n4) return;
    float4 v = ((const float4*)src)[i];
    uint2 o = make_uint2(pack2h(v.x, v.y), pack2h(v.z, v.w));
    if (W == 0)      ((uint2*)g_xh)[i]  = o;
    else if (W == 1) ((uint2*)g_w1h)[i] = o;
    else             ((uint2*)g_w2h)[i] = o;
}

// ---------------------------------------------------------------------------
// fp16 NT GEMM via mma.sync: 64x128 block, 256 thr, 8 warps (2x4, 32x32 warp
// tiles). launch_bounds(256,4): 64-reg cap -> 4 CTAs/SM (RF limiter).
// Single sync per k-tile; double-buffered cp.async; 80B pitch smem.
// MODE 0: qkv = x @ w1^T + b, fused RoPE epilogue.  MODE 1: y @ w2^T + b.
// ---------------------------------------------------------------------------
#define T_AH 0
#define T_BH 5120           // 64 rows * 80B
#define STAGE_BYTES 15360   // (64 + 128) rows * 80B
#define GEMM_SMEM (2*STAGE_BYTES)

#define ROPE_LN_OVER_32 0.2878231366242557f   // ln(10000)/32

// Epilogue scatter with fused RoPE. v = (col d, col d+1), d even.
__device__ __forceinline__ void scatter_qkv(int m, int n, float2 v)
{
    const int which = n >> 10, c = n & 1023;
    const int h = c >> 6, d = c & 63;
    const int b = m >> 10, t = m & 1023, bh = b * NHEAD + h;
    if (which == 2) {
        size_t i0 = ((size_t)bh * HDIM + d) * Tt + t;
        g_Vth[i0]      = __float2half(v.x);
        g_Vth[i0 + Tt] = __float2half(v.y);
        return;
    }
    const float inv = expf(-(float)(d >> 1) * ROPE_LN_OVER_32);
    float sv, cv;
    sincosf((float)t * inv, &sv, &cv);
    float r1 = v.x * cv - v.y * sv;
    float r2 = v.y * cv + v.x * sv;
    const size_t base = ((size_t)bh * Tt + t) * HDIM + d;
    if (which == 0) {
        *(uint32_t*)&g_Qh[base] = pack2h(r1 * 0.125f, r2 * 0.125f);
    } else {
        *(uint32_t*)&g_Kh[base] = pack2h(r1, r2);
    }
}

template<int MODE>
__global__ __launch_bounds__(256, 4)
void gemm_fp16(const float* __restrict__ bias, float* __restrict__ Cout)
{
    extern __shared__ char smem[];
    const uint32_t sb = smem_u32(smem);
    const int tid  = threadIdx.x;
    const int lane = tid & 31, wid = tid >> 5;
    const int wm = wid >> 2, wn = wid & 3;         // 2 x 4 warp grid, 32x32 tiles
    const int m0 = blockIdx.y * 64, n0 = blockIdx.x * 128;

    const __half* Ah = (MODE == 0) ? g_xh  : g_yh;
    const __half* Bh = (MODE == 0) ? g_w1h : g_w2h;

    // cp.async: 768 16B pieces per stage (192 rows x 4), 3 per thread
    const __half* srcs[3];
    uint32_t soff[3];
    #pragma unroll
    for (int j = 0; j < 3; j++) {
        const int idx = tid + 256 * j;
        const int row = idx >> 2, c16 = idx & 3;
        soff[j] = (uint32_t)row * 80 + c16 * 16;
        srcs[j] = (row < 64)
                ? Ah + (size_t)(m0 + row) * Cc + c16 * 8
                : Bh + (size_t)(n0 + row - 64) * Cc + c16 * 8;
    }

    const int jq = lane >> 3, rr = lane & 7;
    const int aRow  = wm * 32 + (jq & 1) * 8 + rr;   // + mf*16
    const int aColB = (jq >> 1) * 16;                // + kk*32
    const int bRow  = wn * 32 + (jq >> 1) * 8 + rr;  // + pf*16
    const int bColB = (jq & 1) * 16;

    float acc[2][4][4];
    #pragma unroll
    for (int i = 0; i < 2; i++)
        #pragma unroll
        for (int j = 0; j < 4; j++)
            #pragma unroll
            for (int e = 0; e < 4; e++) acc[i][j][e] = 0.0f;

    #pragma unroll
    for (int j = 0; j < 3; j++) CP16(sb + soff[j], srcs[j]);
    CP_COMMIT();

    for (int kt = 0; kt < KT; kt++) {
        CP_WAIT0();
        __syncthreads();           // stage kt visible; stage (kt+1)&1 free
        if (kt + 1 < KT) {
            const uint32_t sdst = sb + ((kt + 1) & 1) * STAGE_BYTES;
            const int ko = (kt + 1) * 32;
            #pragma unroll
            for (int j = 0; j < 3; j++) CP16(sdst + soff[j], srcs[j] + ko);
            CP_COMMIT();
        }

        const uint32_t base = sb + (kt & 1) * STAGE_BYTES;
        #pragma unroll
        for (int kk = 0; kk < 2; kk++) {
            const uint32_t kB = kk * 32;
            uint32_t ah[2][4], bh[2][4];
            #pragma unroll
            for (int mf = 0; mf < 2; mf++) {
                uint32_t addr = base + (uint32_t)(aRow + mf * 16) * 80 + aColB + kB;
                LDSM4(ah[mf][0], ah[mf][1], ah[mf][2], ah[mf][3], addr + T_AH);
            }
            #pragma unroll
            for (int pf = 0; pf < 2; pf++) {
                uint32_t addr = base + (uint32_t)(bRow + pf * 16) * 80 + bColB + kB;
                LDSM4(bh[pf][0], bh[pf][1], bh[pf][2], bh[pf][3], addr + T_BH);
            }
            #pragma unroll
            for (int mf = 0; mf < 2; mf++) {
                #pragma unroll
                for (int nt = 0; nt < 4; nt++) {
                    const int pf = nt >> 1, ix = (nt & 1) * 2;
                    mma16816(acc[mf][nt], ah[mf], bh[pf][ix], bh[pf][ix + 1]);
                }
            }
        }
    }

    const int gid = lane >> 2, tg = lane & 3;
    #pragma unroll
    for (int mf = 0; mf < 2; mf++) {
        #pragma unroll
        for (int nt = 0; nt < 4; nt++) {
            const int n = n0 + wn * 32 + nt * 8 + tg * 2;
            const float2 bv = *(const float2*)&bias[n];
            const int mA = m0 + wm * 32 + mf * 16 + gid;
            float2 v01 = make_float2(acc[mf][nt][0] + bv.x, acc[mf][nt][1] + bv.y);
            float2 v23 = make_float2(acc[mf][nt][2] + bv.x, acc[mf][nt][3] + bv.y);
            if (MODE == 0) {
                scatter_qkv(mA,     n, v01);
                scatter_qkv(mA + 8, n, v23);
            } else {
                *(float2*)&Cout[(size_t)mA * Cc + n]       = v01;
                *(float2*)&Cout[(size_t)(mA + 8) * Cc + n] = v23;
            }
        }
    }
}

// ---------------------------------------------------------------------------
// Tensor-core flash attention (fp16), causal. Block = (qt, bh), 128 thr.
// K/V double-buffered via cp.async; single sync per k-tile.
// carveout=100 -> 4 CTAs/SM (was smem-limited to 2 at default carveout).
// ---------------------------------------------------------------------------
#define FPITCH 144
#define SQH 0
#define SKV0 9216
#define KV_STAGE 18432
#define FL_SMEM 46080

__global__ __launch_bounds__(128)
void flash_attn_kernel()
{
    extern __shared__ char smem[];
    const uint32_t sb = smem_u32(smem);
    const int tid  = threadIdx.x;
    const int lane = tid & 31, w = tid >> 5;
    const int qt = blockIdx.x;     // 0..15
    const int bh = blockIdx.y;     // 0..127

    const __half* Qh = g_Qh  + ((size_t)bh * Tt + qt * 64) * HDIM;
    const __half* Kh = g_Kh  + (size_t)bh * Tt * HDIM;
    const __half* Vh = g_Vth + (size_t)bh * HDIM * Tt;

    #pragma unroll
    for (int ii = 0; ii < 4; ii++) {
        int idx = tid + 128 * ii;
        int r = idx >> 3, c8 = (idx & 7) * 8;
        uint32_t so = (uint32_t)r * FPITCH + c8 * 2;
        *(uint4*)(smem + SQH + so) = *(const uint4*)&Qh[r * 64 + c8];
    }

    const int jq = lane >> 3, rr = lane & 7;
    const uint32_t aAddr = sb + (uint32_t)(w * 16 + (lane & 15)) * FPITCH
                         + (lane >> 4) * 16;
    const uint32_t bBase = (uint32_t)((jq >> 1) * 8 + rr) * FPITCH
                         + (jq & 1) * 16;

    const int gid = lane >> 2, tg = lane & 3;
    const int rowA = w * 16 + gid;
    const int rowB = rowA + 8;

    float o[8][4];
    #pragma unroll
    for (int nt = 0; nt < 8; nt++)
        #pragma unroll
        for (int e = 0; e < 4; e++) o[nt][e] = 0.0f;
    float mA = -1e30f, mB = -1e30f, lA = 0.0f, lB = 0.0f;

    #pragma unroll
    for (int ii = 0; ii < 4; ii++) {
        int idx = tid + 128 * ii;
        int r = idx >> 3, c8 = (idx & 7) * 8;
        uint32_t so = (uint32_t)r * FPITCH + c8 * 2;
        CP16(sb + SKV0 + so,        &Kh[(size_t)r * 64 + c8]);
        CP16(sb + SKV0 + 9216 + so, &Vh[(size_t)r * Tt + c8]);
    }
    CP_COMMIT();

    for (int kt = 0; kt <= qt; kt++) {
        CP_WAIT0();
        __syncthreads();
        if (kt < qt) {
            const uint32_t sdst = sb + SKV0 + ((kt + 1) & 1) * KV_STAGE;
            #pragma unroll
            for (int ii = 0; ii < 4; ii++) {
                int idx = tid + 128 * ii;
                int r = idx >> 3, c8 = (idx & 7) * 8;
                uint32_t so = (uint32_t)r * FPITCH + c8 * 2;
                CP16(sdst + so,        &Kh[((kt + 1) * 64 + r) * 64 + c8]);
                CP16(sdst + 9216 + so, &Vh[(size_t)r * Tt + (kt + 1) * 64 + c8]);
            }
            CP_COMMIT();
        }

        const uint32_t kvb = sb + SKV0 + (kt & 1) * KV_STAGE;

        float c[8][4];
        #pragma unroll
        for (int nt = 0; nt < 8; nt++)
            #pragma unroll
            for (int e = 0; e < 4; e++) c[nt][e] = 0.0f;

        #pragma unroll
        for (int kk = 0; kk < 4; kk++) {
            uint32_t aH[4];
            LDSM4(aH[0], aH[1], aH[2], aH[3], aAddr + SQH + kk * 32);
            #pragma unroll
            for (int pf = 0; pf < 4; pf++) {
                uint32_t bH[4];
                uint32_t ba = kvb + bBase + (uint32_t)pf * 16 * FPITCH + kk * 32;
                LDSM4(bH[0], bH[1], bH[2], bH[3], ba);
                const int nt0 = pf * 2;
                mma16816(c[nt0],     aH, bH[0], bH[1]);
                mma16816(c[nt0 + 1], aH, bH[2], bH[3]);
            }
        }

        if (kt == qt) {
            #pragma unroll
            for (int nt = 0; nt < 8; nt++) {
                const int colb = nt * 8 + tg * 2;
                if (colb     > rowA) c[nt][0] = -1e30f;
                if (colb + 1 > rowA) c[nt][1] = -1e30f;
                if (colb     > rowB) c[nt][2] = -1e30f;
                if (colb + 1 > rowB) c[nt][3] = -1e30f;
            }
        }

        float tmA = -1e30f, tmB = -1e30f;
        #pragma unroll
        for (int nt = 0; nt < 8; nt++) {
            tmA = fmaxf(tmA, fmaxf(c[nt][0], c[nt][1]));
            tmB = fmaxf(tmB, fmaxf(c[nt][2], c[nt][3]));
        }
        tmA = fmaxf(tmA, __shfl_xor_sync(0xffffffffu, tmA, 1));
        tmA = fmaxf(tmA, __shfl_xor_sync(0xffffffffu, tmA, 2));
        tmB = fmaxf(tmB, __shfl_xor_sync(0xffffffffu, tmB, 1));
        tmB = fmaxf(tmB, __shfl_xor_sync(0xffffffffu, tmB, 2));

        const float mnA = fmaxf(mA, tmA), mnB = fmaxf(mB, tmB);
        const float alA = __expf(mA - mnA), alB = __expf(mB - mnB);
        mA = mnA; mB = mnB;

        float sA = 0.0f, sB = 0.0f;
        #pragma unroll
        for (int nt = 0; nt < 8; nt++) {
            c[nt][0] = __expf(c[nt][0] - mnA); sA += c[nt][0];
            c[nt][1] = __expf(c[nt][1] - mnA); sA += c[nt][1];
            c[nt][2] = __expf(c[nt][2] - mnB); sB += c[nt][2];
            c[nt][3] = __expf(c[nt][3] - mnB); sB += c[nt][3];
        }
        sA += __shfl_xor_sync(0xffffffffu, sA, 1);
        sA += __shfl_xor_sync(0xffffffffu, sA, 2);
        sB += __shfl_xor_sync(0xffffffffu, sB, 1);
        sB += __shfl_xor_sync(0xffffffffu, sB, 2);
        lA = lA * alA + sA;
        lB = lB * alB + sB;
        #pragma unroll
        for (int nt = 0; nt < 8; nt++) {
            o[nt][0] *= alA; o[nt][1] *= alA;
            o[nt][2] *= alB; o[nt][3] *= alB;
        }

        #pragma unroll
        for (int ks = 0; ks < 4; ks++) {
            uint32_t pH[4];
            pH[0] = pack2h(c[2*ks][0],     c[2*ks][1]);
            pH[1] = pack2h(c[2*ks][2],     c[2*ks][3]);
            pH[2] = pack2h(c[2*ks + 1][0], c[2*ks + 1][1]);
            pH[3] = pack2h(c[2*ks + 1][2], c[2*ks + 1][3]);
            #pragma unroll
            for (int pfd = 0; pfd < 4; pfd++) {
                uint32_t bH[4];
                uint32_t ba = kvb + 9216 + bBase + (uint32_t)pfd * 16 * FPITCH + ks * 32;
                LDSM4(bH[0], bH[1], bH[2], bH[3], ba);
                const int nd = pfd * 2;
                mma16816(o[nd],     pH, bH[0], bH[1]);
                mma16816(o[nd + 1], pH, bH[2], bH[3]);
            }
        }
    }

    const int b = bh >> 4, h = bh & 15;
    const float invA = 1.0f / lA, invB = 1.0f / lB;
    const size_t ybA = ((size_t)(b * Tt + qt * 64 + rowA)) * Cc + h * HDIM;
    const size_t ybB = ((size_t)(b * Tt + qt * 64 + rowB)) * Cc + h * HDIM;
    #pragma unroll
    for (int nt = 0; nt < 8; nt++) {
        const int d = nt * 8 + tg * 2;
        *(uint32_t*)&g_yh[ybA + d] = pack2h(o[nt][0] * invA, o[nt][1] * invA);
        *(uint32_t*)&g_yh[ybB + d] = pack2h(o[nt][2] * invB, o[nt][3] * invB);
    }
}

// ---------------------------------------------------------------------------
extern "C" void kernel_launch(void* const* d_in, const int* in_sizes, int n_in,
                              void* d_out, int out_size)
{
    (void)in_sizes; (void)n_in; (void)out_size;
    const float* x   = (const float*)d_in[0];
    const float* ipw = (const float*)d_in[1];
    const float* ipb = (const float*)d_in[2];
    const float* opw = (const float*)d_in[3];
    const float* opb = (const float*)d_in[4];
    float* out = (float*)d_out;

    cudaFuncSetAttribute(gemm_fp16<0>,
                         cudaFuncAttributeMaxDynamicSharedMemorySize, GEMM_SMEM);
    cudaFuncSetAttribute(gemm_fp16<1>,
                         cudaFuncAttributeMaxDynamicSharedMemorySize, GEMM_SMEM);
    cudaFuncSetAttribute(flash_attn_kernel,
                         cudaFuncAttributeMaxDynamicSharedMemorySize, FL_SMEM);
    // full 228KB smem config: GEMM 4x30.7KB, flash 4x46KB resident
    cudaFuncSetAttribute(gemm_fp16<0>,
                         cudaFuncAttributePreferredSharedMemoryCarveout, 100);
    cudaFuncSetAttribute(gemm_fp16<1>,
                         cudaFuncAttributePreferredSharedMemoryCarveout, 100);
    cudaFuncSetAttribute(flash_attn_kernel,
                         cudaFuncAttributePreferredSharedMemoryCarveout, 100);

    // 0) fp16 conversions
    cvt_kernel<0><<<(Mm*Cc/4 + 255)/256, 256>>>(x,   Mm*Cc/4);
    cvt_kernel<1><<<(N1*Cc/4 + 255)/256, 256>>>(ipw, N1*Cc/4);
    cvt_kernel<2><<<(Cc*Cc/4 + 255)/256, 256>>>(opw, Cc*Cc/4);

    // 1) QKV projection + bias + fused RoPE -> Qh, Kh, Vt (fp16)
    {
        dim3 grid(N1 / 128, Mm / 64);    // (24, 128)
        gemm_fp16<0><<<grid, 256, GEMM_SMEM>>>(ipb, nullptr);
    }

    // 2) tensor-core causal flash attention (async K/V pipeline) -> g_yh
    {
        dim3 grid(Tt / 64, BHt);
        flash_attn_kernel<<<grid, 128, FL_SMEM>>>();
    }

    // 3) output projection + bias
    {
        dim3 grid(Cc / 128, Mm / 64);    // (8, 128)
        gemm_fp16<1><<<grid, 256, GEMM_SMEM>>>(opb, out);
    }
}

// round 16
// speedup vs baseline: 1.1839x; 1.0255x over previous
#include <cuda_runtime.h>
#include <cuda_fp16.h>
#include <math.h>
#include <stdint.h>

#define Bb 8
#define Tt 1024
#define Cc 1024
#define NHEAD 16
#define HDIM 64
#define BHt (Bb*NHEAD)     // 128
#define Mm (Bb*Tt)         // 8192
#define N1 (3*Cc)          // 3072
#define KT 32              // 1024/32 k-tiles

// ------------------------- device scratch (no allocs allowed) --------------
__device__ __half g_xh [(size_t)Mm*Cc];
__device__ __half g_w1h[(size_t)N1*Cc];
__device__ __half g_w2h[(size_t)Cc*Cc];
__device__ __half g_yh [(size_t)Mm*Cc];
__device__ __half g_Qh [(size_t)BHt*Tt*HDIM];   // post-rope, x0.125
__device__ __half g_Kh [(size_t)BHt*Tt*HDIM];   // post-rope
__device__ __half g_Vth[(size_t)BHt*HDIM*Tt];   // [bh][d][t]

// ------------------------------ PTX helpers --------------------------------
__device__ __forceinline__ uint32_t smem_u32(const void* p) {
    uint32_t a;
    asm("{ .reg .u64 t; cvta.to.shared.u64 t, %1; cvt.u32.u64 %0, t; }"
        : "=r"(a) : "l"(p));
    return a;
}

#define CP16(dst, src) \
    asm volatile("cp.async.cg.shared.global [%0], [%1], 16;" \
                 :: "r"(dst), "l"(src) : "memory")
#define CP_COMMIT() asm volatile("cp.async.commit_group;" ::: "memory")
#define CP_WAIT0()  asm volatile("cp.async.wait_group 0;" ::: "memory")

#define LDSM4(r0, r1, r2, r3, a) \
    asm volatile("ldmatrix.sync.aligned.m8n8.x4.shared.b16 {%0,%1,%2,%3}, [%4];" \
                 : "=r"(r0), "=r"(r1), "=r"(r2), "=r"(r3) : "r"(a))

__device__ __forceinline__ void mma16816(float c[4], const uint32_t a[4],
                                         uint32_t b0, uint32_t b1) {
    asm volatile("mma.sync.aligned.m16n8k16.row.col.f32.f16.f16.f32 "
                 "{%0,%1,%2,%3}, {%4,%5,%6,%7}, {%8,%9}, {%0,%1,%2,%3};"
                 : "+f"(c[0]), "+f"(c[1]), "+f"(c[2]), "+f"(c[3])
                 : "r"(a[0]), "r"(a[1]), "r"(a[2]), "r"(a[3]),
                   "r"(b0), "r"(b1));
}

__device__ __forceinline__ uint32_t pack2h(float x, float y) {
    __half2 h = __floats2half2_rn(x, y);
    return *reinterpret_cast<uint32_t*>(&h);
}

// ---------------------------------------------------------------------------
// fp32 -> fp16 conversion for x, w1, w2 in ONE launch.
// ---------------------------------------------------------------------------
#define NX4  ((size_t)Mm*Cc/4)     // 2097152
#define NW14 ((size_t)N1*Cc/4)     //  786432
#define NW24 ((size_t)Cc*Cc/4)     //  262144

__global__ __launch_bounds__(256)
void cvt_all_kernel(const float* __restrict__ x,
                    const float* __restrict__ w1,
                    const float* __restrict__ w2)
{
    size_t i = (size_t)blockIdx.x * blockDim.x + threadIdx.x;
    const float* src;
    __half* dst;
    size_t j;
    if (i < NX4)               { src = x;  dst = g_xh;  j = i; }
    else if (i < NX4 + NW14)   { src = w1; dst = g_w1h; j = i - NX4; }
    else                       { src = w2; dst = g_w2h; j = i - NX4 - NW14; }
    float4 v = ((const float4*)src)[j];
    ((uint2*)dst)[j] = make_uint2(pack2h(v.x, v.y), pack2h(v.z, v.w));
}

// ---------------------------------------------------------------------------
// fp16 NT GEMM via mma.sync: 128x128 block, 512 thr, 16 warps (4x4, 32x32
// warp tiles). launch_bounds(512,2): 64-reg cap -> 2 CTAs/SM = 32 warps
// (same warps as R15) but B-tile reuse doubles: L2 traffic -33%.
// Single sync per k-tile; double-buffered cp.async; 80B pitch smem.
// MODE 0: qkv = x @ w1^T + b, fused RoPE epilogue.  MODE 1: y @ w2^T + b.
// ---------------------------------------------------------------------------
#define T_AH 0
#define T_BH 10240          // 128 rows * 80B
#define STAGE_BYTES 20480   // 256 rows * 80B
#define GEMM_SMEM (2*STAGE_BYTES)

#define ROPE_LN_OVER_32 0.2878231366242557f   // ln(10000)/32

// Epilogue scatter with fused RoPE. v = (col d, col d+1), d even.
__device__ __forceinline__ void scatter_qkv(int m, int n, float2 v)
{
    const int which = n >> 10, c = n & 1023;
    const int h = c >> 6, d = c & 63;
    const int b = m >> 10, t = m & 1023, bh = b * NHEAD + h;
    if (which == 2) {
        size_t i0 = ((size_t)bh * HDIM + d) * Tt + t;
        g_Vth[i0]      = __float2half(v.x);
        g_Vth[i0 + Tt] = __float2half(v.y);
        return;
    }
    const float inv = expf(-(float)(d >> 1) * ROPE_LN_OVER_32);
    float sv, cv;
    sincosf((float)t * inv, &sv, &cv);
    float r1 = v.x * cv - v.y * sv;
    float r2 = v.y * cv + v.x * sv;
    const size_t base = ((size_t)bh * Tt + t) * HDIM + d;
    if (which == 0) {
        *(uint32_t*)&g_Qh[base] = pack2h(r1 * 0.125f, r2 * 0.125f);
    } else {
        *(uint32_t*)&g_Kh[base] = pack2h(r1, r2);
    }
}

template<int MODE>
__global__ __launch_bounds__(512, 2)
void gemm_fp16(const float* __restrict__ bias, float* __restrict__ Cout)
{
    extern __shared__ char smem[];
    const uint32_t sb = smem_u32(smem);
    const int tid  = threadIdx.x;
    const int lane = tid & 31, wid = tid >> 5;
    const int wm = wid >> 2, wn = wid & 3;         // 4 x 4 warp grid, 32x32 tiles
    const int m0 = blockIdx.y * 128, n0 = blockIdx.x * 128;

    const __half* Ah = (MODE == 0) ? g_xh  : g_yh;
    const __half* Bh = (MODE == 0) ? g_w1h : g_w2h;

    // cp.async: 1024 16B pieces per stage (256 rows x 4), 2 per thread
    const __half* srcs[2];
    uint32_t soff[2];
    #pragma unroll
    for (int j = 0; j < 2; j++) {
        const int idx = tid + 512 * j;
        const int row = idx >> 2, c16 = idx & 3;
        soff[j] = (uint32_t)row * 80 + c16 * 16;
        srcs[j] = (row < 128)
                ? Ah + (size_t)(m0 + row) * Cc + c16 * 8
                : Bh + (size_t)(n0 + row - 128) * Cc + c16 * 8;
    }

    const int jq = lane >> 3, rr = lane & 7;
    const int aRow  = wm * 32 + (jq & 1) * 8 + rr;   // + mf*16
    const int aColB = (jq >> 1) * 16;                // + kk*32
    const int bRow  = wn * 32 + (jq >> 1) * 8 + rr;  // + pf*16
    const int bColB = (jq & 1) * 16;

    float acc[2][4][4];
    #pragma unroll
    for (int i = 0; i < 2; i++)
        #pragma unroll
        for (int j = 0; j < 4; j++)
            #pragma unroll
            for (int e = 0; e < 4; e++) acc[i][j][e] = 0.0f;

    #pragma unroll
    for (int j = 0; j < 2; j++) CP16(sb + soff[j], srcs[j]);
    CP_COMMIT();

    for (int kt = 0; kt < KT; kt++) {
        CP_WAIT0();
        __syncthreads();           // stage kt visible; stage (kt+1)&1 free
        if (kt + 1 < KT) {
            const uint32_t sdst = sb + ((kt + 1) & 1) * STAGE_BYTES;
            const int ko = (kt + 1) * 32;
            #pragma unroll
            for (int j = 0; j < 2; j++) CP16(sdst + soff[j], srcs[j] + ko);
            CP_COMMIT();
        }

        const uint32_t base = sb + (kt & 1) * STAGE_BYTES;
        #pragma unroll
        for (int kk = 0; kk < 2; kk++) {
            const uint32_t kB = kk * 32;
            uint32_t ah[2][4], bh[2][4];
            #pragma unroll
            for (int mf = 0; mf < 2; mf++) {
                uint32_t addr = base + (uint32_t)(aRow + mf * 16) * 80 + aColB + kB;
                LDSM4(ah[mf][0], ah[mf][1], ah[mf][2], ah[mf][3], addr + T_AH);
            }
            #pragma unroll
            for (int pf = 0; pf < 2; pf++) {
                uint32_t addr = base + (uint32_t)(bRow + pf * 16) * 80 + bColB + kB;
                LDSM4(bh[pf][0], bh[pf][1], bh[pf][2], bh[pf][3], addr + T_BH);
            }
            #pragma unroll
            for (int mf = 0; mf < 2; mf++) {
                #pragma unroll
                for (int nt = 0; nt < 4; nt++) {
                    const int pf = nt >> 1, ix = (nt & 1) * 2;
                    mma16816(acc[mf][nt], ah[mf], bh[pf][ix], bh[pf][ix + 1]);
                }
            }
        }
    }

    const int gid = lane >> 2, tg = lane & 3;
    #pragma unroll
    for (int mf = 0; mf < 2; mf++) {
        #pragma unroll
        for (int nt = 0; nt < 4; nt++) {
            const int n = n0 + wn * 32 + nt * 8 + tg * 2;
            const float2 bv = *(const float2*)&bias[n];
            const int mA = m0 + wm * 32 + mf * 16 + gid;
            float2 v01 = make_float2(acc[mf][nt][0] + bv.x, acc[mf][nt][1] + bv.y);
            float2 v23 = make_float2(acc[mf][nt][2] + bv.x, acc[mf][nt][3] + bv.y);
            if (MODE == 0) {
                scatter_qkv(mA,     n, v01);
                scatter_qkv(mA + 8, n, v23);
            } else {
                *(float2*)&Cout[(size_t)mA * Cc + n]       = v01;
                *(float2*)&Cout[(size_t)(mA + 8) * Cc + n] = v23;
            }
        }
    }
}

// ---------------------------------------------------------------------------
// Tensor-core flash attention (fp16), causal. Block = (qt, bh), 128 thr.
// K/V double-buffered via cp.async; single sync per k-tile; longest q-tiles
// scheduled first (qt reversed) to shrink the triangular-load wave tail.
// ---------------------------------------------------------------------------
#define FPITCH 144
#define SQH 0
#define SKV0 9216
#define KV_STAGE 18432
#define FL_SMEM 46080

__global__ __launch_bounds__(128)
void flash_attn_kernel()
{
    extern __shared__ char smem[];
    const uint32_t sb = smem_u32(smem);
    const int tid  = threadIdx.x;
    const int lane = tid & 31, w = tid >> 5;
    const int qt = (gridDim.x - 1) - blockIdx.x;   // longest blocks first
    const int bh = blockIdx.y;     // 0..127

    const __half* Qh = g_Qh  + ((size_t)bh * Tt + qt * 64) * HDIM;
    const __half* Kh = g_Kh  + (size_t)bh * Tt * HDIM;
    const __half* Vh = g_Vth + (size_t)bh * HDIM * Tt;

    #pragma unroll
    for (int ii = 0; ii < 4; ii++) {
        int idx = tid + 128 * ii;
        int r = idx >> 3, c8 = (idx & 7) * 8;
        uint32_t so = (uint32_t)r * FPITCH + c8 * 2;
        *(uint4*)(smem + SQH + so) = *(const uint4*)&Qh[r * 64 + c8];
    }

    const int jq = lane >> 3, rr = lane & 7;
    const uint32_t aAddr = sb + (uint32_t)(w * 16 + (lane & 15)) * FPITCH
                         + (lane >> 4) * 16;
    const uint32_t bBase = (uint32_t)((jq >> 1) * 8 + rr) * FPITCH
                         + (jq & 1) * 16;

    const int gid = lane >> 2, tg = lane & 3;
    const int rowA = w * 16 + gid;
    const int rowB = rowA + 8;

    float o[8][4];
    #pragma unroll
    for (int nt = 0; nt < 8; nt++)
        #pragma unroll
        for (int e = 0; e < 4; e++) o[nt][e] = 0.0f;
    float mA = -1e30f, mB = -1e30f, lA = 0.0f, lB = 0.0f;

    #pragma unroll
    for (int ii = 0; ii < 4; ii++) {
        int idx = tid + 128 * ii;
        int r = idx >> 3, c8 = (idx & 7) * 8;
        uint32_t so = (uint32_t)r * FPITCH + c8 * 2;
        CP16(sb + SKV0 + so,        &Kh[(size_t)r * 64 + c8]);
        CP16(sb + SKV0 + 9216 + so, &Vh[(size_t)r * Tt + c8]);
    }
    CP_COMMIT();

    for (int kt = 0; kt <= qt; kt++) {
        CP_WAIT0();
        __syncthreads();
        if (kt < qt) {
            const uint32_t sdst = sb + SKV0 + ((kt + 1) & 1) * KV_STAGE;
            #pragma unroll
            for (int ii = 0; ii < 4; ii++) {
                int idx = tid + 128 * ii;
                int r = idx >> 3, c8 = (idx & 7) * 8;
                uint32_t so = (uint32_t)r * FPITCH + c8 * 2;
                CP16(sdst + so,        &Kh[((kt + 1) * 64 + r) * 64 + c8]);
                CP16(sdst + 9216 + so, &Vh[(size_t)r * Tt + (kt + 1) * 64 + c8]);
            }
            CP_COMMIT();
        }

        const uint32_t kvb = sb + SKV0 + (kt & 1) * KV_STAGE;

        float c[8][4];
        #pragma unroll
        for (int nt = 0; nt < 8; nt++)
            #pragma unroll
            for (int e = 0; e < 4; e++) c[nt][e] = 0.0f;

        #pragma unroll
        for (int kk = 0; kk < 4; kk++) {
            uint32_t aH[4];
            LDSM4(aH[0], aH[1], aH[2], aH[3], aAddr + SQH + kk * 32);
            #pragma unroll
            for (int pf = 0; pf < 4; pf++) {
                uint32_t bH[4];
                uint32_t ba = kvb + bBase + (uint32_t)pf * 16 * FPITCH + kk * 32;
                LDSM4(bH[0], bH[1], bH[2], bH[3], ba);
                const int nt0 = pf * 2;
                mma16816(c[nt0],     aH, bH[0], bH[1]);
                mma16816(c[nt0 + 1], aH, bH[2], bH[3]);
            }
        }

        if (kt == qt) {
            #pragma unroll
            for (int nt = 0; nt < 8; nt++) {
                const int colb = nt * 8 + tg * 2;
                if (colb     > rowA) c[nt][0] = -1e30f;
                if (colb + 1 > rowA) c[nt][1] = -1e30f;
                if (colb     > rowB) c[nt][2] = -1e30f;
                if (colb + 1 > rowB) c[nt][3] = -1e30f;
            }
        }

        float tmA = -1e30f, tmB = -1e30f;
        #pragma unroll
        for (int nt = 0; nt < 8; nt++) {
            tmA = fmaxf(tmA, fmaxf(c[nt][0], c[nt][1]));
            tmB = fmaxf(tmB, fmaxf(c[nt][2], c[nt][3]));
        }
        tmA = fmaxf(tmA, __shfl_xor_sync(0xffffffffu, tmA, 1));
        tmA = fmaxf(tmA, __shfl_xor_sync(0xffffffffu, tmA, 2));
        tmB = fmaxf(tmB, __shfl_xor_sync(0xffffffffu, tmB, 1));
        tmB = fmaxf(tmB, __shfl_xor_sync(0xffffffffu, tmB, 2));

        const float mnA = fmaxf(mA, tmA), mnB = fmaxf(mB, tmB);
        const float alA = __expf(mA - mnA), alB = __expf(mB - mnB);
        mA = mnA; mB = mnB;

        float sA = 0.0f, sB = 0.0f;
        #pragma unroll
        for (int nt = 0; nt < 8; nt++) {
            c[nt][0] = __expf(c[nt][0] - mnA); sA += c[nt][0];
            c[nt][1] = __expf(c[nt][1] - mnA); sA += c[nt][1];
            c[nt][2] = __expf(c[nt][2] - mnB); sB += c[nt][2];
            c[nt][3] = __expf(c[nt][3] - mnB); sB += c[nt][3];
        }
        sA += __shfl_xor_sync(0xffffffffu, sA, 1);
        sA += __shfl_xor_sync(0xffffffffu, sA, 2);
        sB += __shfl_xor_sync(0xffffffffu, sB, 1);
        sB += __shfl_xor_sync(0xffffffffu, sB, 2);
        lA = lA * alA + sA;
        lB = lB * alB + sB;
        #pragma unroll
        for (int nt = 0; nt < 8; nt++) {
            o[nt][0] *= alA; o[nt][1] *= alA;
            o[nt][2] *= alB; o[nt][3] *= alB;
        }

        #pragma unroll
        for (int ks = 0; ks < 4; ks++) {
            uint32_t pH[4];
            pH[0] = pack2h(c[2*ks][0],     c[2*ks][1]);
            pH[1] = pack2h(c[2*ks][2],     c[2*ks][3]);
            pH[2] = pack2h(c[2*ks + 1][0], c[2*ks + 1][1]);
            pH[3] = pack2h(c[2*ks + 1][2], c[2*ks + 1][3]);
            #pragma unroll
            for (int pfd = 0; pfd < 4; pfd++) {
                uint32_t bH[4];
                uint32_t ba = kvb + 9216 + bBase + (uint32_t)pfd * 16 * FPITCH + ks * 32;
                LDSM4(bH[0], bH[1], bH[2], bH[3], ba);
                const int nd = pfd * 2;
                mma16816(o[nd],     pH, bH[0], bH[1]);
                mma16816(o[nd + 1], pH, bH[2], bH[3]);
            }
        }
    }

    const int b = bh >> 4, h = bh & 15;
    const float invA = 1.0f / lA, invB = 1.0f / lB;
    const size_t ybA = ((size_t)(b * Tt + qt * 64 + rowA)) * Cc + h * HDIM;
    const size_t ybB = ((size_t)(b * Tt + qt * 64 + rowB)) * Cc + h * HDIM;
    #pragma unroll
    for (int nt = 0; nt < 8; nt++) {
        const int d = nt * 8 + tg * 2;
        *(uint32_t*)&g_yh[ybA + d] = pack2h(o[nt][0] * invA, o[nt][1] * invA);
        *(uint32_t*)&g_yh[ybB + d] = pack2h(o[nt][2] * invB, o[nt][3] * invB);
    }
}

// ---------------------------------------------------------------------------
extern "C" void kernel_launch(void* const* d_in, const int* in_sizes, int n_in,
                              void* d_out, int out_size)
{
    (void)in_sizes; (void)n_in; (void)out_size;
    const float* x   = (const float*)d_in[0];
    const float* ipw = (const float*)d_in[1];
    const float* ipb = (const float*)d_in[2];
    const float* opw = (const float*)d_in[3];
    const float* opb = (const float*)d_in[4];
    float* out = (float*)d_out;

    cudaFuncSetAttribute(gemm_fp16<0>,
                         cudaFuncAttributeMaxDynamicSharedMemorySize, GEMM_SMEM);
    cudaFuncSetAttribute(gemm_fp16<1>,
                         cudaFuncAttributeMaxDynamicSharedMemorySize, GEMM_SMEM);
    cudaFuncSetAttribute(flash_attn_kernel,
                         cudaFuncAttributeMaxDynamicSharedMemorySize, FL_SMEM);
    cudaFuncSetAttribute(gemm_fp16<0>,
                         cudaFuncAttributePreferredSharedMemoryCarveout, 100);
    cudaFuncSetAttribute(gemm_fp16<1>,
                         cudaFuncAttributePreferredSharedMemoryCarveout, 100);
    cudaFuncSetAttribute(flash_attn_kernel,
                         cudaFuncAttributePreferredSharedMemoryCarveout, 100);

    // 0) fp16 conversions (single launch for x, w1, w2)
    {
        const size_t total = NX4 + NW14 + NW24;   // 3145728
        cvt_all_kernel<<<(unsigned)((total + 255) / 256), 256>>>(x, ipw, opw);
    }

    // 1) QKV projection + bias + fused RoPE -> Qh, Kh, Vt (fp16)
    {
        dim3 grid(N1 / 128, Mm / 128);   // (24, 64)
        gemm_fp16<0><<<grid, 512, GEMM_SMEM>>>(ipb, nullptr);
    }

    // 2) tensor-core causal flash attention (async K/V pipeline) -> g_yh
    {
        dim3 grid(Tt / 64, BHt);
        flash_attn_kernel<<<grid, 128, FL_SMEM>>>();
    }

    // 3) output projection + bias
    {
        dim3 grid(Cc / 128, Mm / 128);   // (8, 64)
        gemm_fp16<1><<<grid, 512, GEMM_SMEM>>>(opb, out);
    }
}